// round 10
// baseline (speedup 1.0000x reference)
#include <cuda_runtime.h>
#include <cuda_fp16.h>
#include <math.h>
#include <stdint.h>

// Problem constants
#define Bn   4
#define Sn   2048
#define Dn   1024
#define Hn   16
#define HDn  64
#define HHD  (Hn*HDn)      // 1024
#define QKVROW (3*HHD)     // 3072
#define Mrows (Bn*Sn)      // 8192

// Q pre-scale: rsqrt(64) * log2(e)  (softmax done in exp2 domain)
#define QSCALE 0.1803368801111f

// ---------------- scratch (allocation-free device globals) ----------------
__device__ __align__(128) __half g_x[(size_t)Mrows * Dn];
__device__ __align__(128) __half g_wqkv[(size_t)Dn * QKVROW];   // [K][N] fp16
__device__ __align__(128) __half g_wproj[(size_t)HHD * Dn];     // [K][N] fp16
__device__ __align__(128) __half g_q[(size_t)Bn * Hn * Sn * HDn];
__device__ __align__(128) __half g_k[(size_t)Bn * Hn * Sn * HDn];
__device__ __align__(128) __half g_v[(size_t)Bn * Hn * Sn * HDn];
__device__ __align__(128) __half g_att[(size_t)Mrows * HHD];

// ---------------- PTX helpers ----------------
__device__ __forceinline__ uint32_t smem_u32(const void* p) {
    uint32_t a;
    asm("{ .reg .u64 t; cvta.to.shared.u64 t, %1; cvt.u32.u64 %0, t; }" : "=r"(a) : "l"(p));
    return a;
}
#define CP16(s, g) asm volatile("cp.async.cg.shared.global [%0], [%1], 16;" :: "r"(s), "l"(g))
#define CP_COMMIT() asm volatile("cp.async.commit_group;" ::: "memory")
#define CP_WAITG(n) asm volatile("cp.async.wait_group %0;" :: "n"(n) : "memory")

__device__ __forceinline__ void ldsm_x4(uint32_t (&r)[4], uint32_t addr) {
    asm volatile("ldmatrix.sync.aligned.m8n8.x4.shared.b16 {%0,%1,%2,%3}, [%4];"
                 : "=r"(r[0]), "=r"(r[1]), "=r"(r[2]), "=r"(r[3]) : "r"(addr));
}
__device__ __forceinline__ void ldsm_x4_t(uint32_t (&r)[4], uint32_t addr) {
    asm volatile("ldmatrix.sync.aligned.m8n8.x4.trans.shared.b16 {%0,%1,%2,%3}, [%4];"
                 : "=r"(r[0]), "=r"(r[1]), "=r"(r[2]), "=r"(r[3]) : "r"(addr));
}
__device__ __forceinline__ void mma_f16(float (&c)[4], const uint32_t (&a)[4],
                                        uint32_t b0, uint32_t b1) {
    asm volatile(
        "mma.sync.aligned.m16n8k16.row.col.f32.f16.f16.f32 "
        "{%0,%1,%2,%3}, {%4,%5,%6,%7}, {%8,%9}, {%0,%1,%2,%3};"
        : "+f"(c[0]), "+f"(c[1]), "+f"(c[2]), "+f"(c[3])
        : "r"(a[0]), "r"(a[1]), "r"(a[2]), "r"(a[3]), "r"(b0), "r"(b1));
}
__device__ __forceinline__ uint32_t pack_f16(float lo, float hi) {
    uint32_t r;
    asm("cvt.rn.f16x2.f32 %0, %1, %2;" : "=r"(r) : "f"(hi), "f"(lo));
    return r;
}
__device__ __forceinline__ float ex2(float x) {
    float r;
    asm("ex2.approx.ftz.f32 %0, %1;" : "=f"(r) : "f"(x));
    return r;
}
// XOR-swizzled smem offset for 128B rows (byte offset); c = 16B chunk 0..7
#define SWZ(row, c) ((uint32_t)((row) * 128 + (((c) ^ ((row) & 7)) << 4)))
// 512B-row B tile: per-128B-quarter XOR swizzle; ncol = fp16 column 0..255
__device__ __forceinline__ uint32_t bswz(int row, int ncol) {
    int ch = ncol >> 3;            // 16B chunk 0..31
    return (uint32_t)(row * 512 + ((ch >> 3) << 7) + (((ch & 7) ^ (row & 7)) << 4));
}

// ---------------- fused prep kernel ----------------
#define NX4  ((Mrows * Dn) / 4)
#define NW14 ((Dn * QKVROW) / 4)
#define NW24 ((HHD * Dn) / 4)

__global__ __launch_bounds__(256) void prep_kernel(
    const float* __restrict__ x, const float* __restrict__ wq_in,
    const float* __restrict__ wp_in,
    __half* __restrict__ xh, __half* __restrict__ wq, __half* __restrict__ wp)
{
    int i = blockIdx.x * 256 + threadIdx.x;
    const float* src;
    __half* dst;
    int j;
    if (i < NX4) {
        src = x; dst = xh; j = i;
    } else if (i < NX4 + NW14) {
        src = wq_in; dst = wq; j = i - NX4;
    } else {
        src = wp_in; dst = wp; j = i - NX4 - NW14;
    }
    float4 v = ((const float4*)src)[j];
    ((uint32_t*)dst)[j * 2 + 0] = pack_f16(v.x, v.y);
    ((uint32_t*)dst)[j * 2 + 1] = pack_f16(v.z, v.w);
}

// ---------------- plain fp16 GEMM: 512 threads, 128x256 tile, BK=64 ----------
#define BM 128
#define BN 256
#define BKc 64
#define A_BYTES (BM * 128)              // 16384
#define B_BYTES (BKc * 512)             // 32768
#define STAGE   (A_BYTES + B_BYTES)     // 49152
#define SMEM_G  (2 * STAGE)             // 98304
#define GTHREADS 512

// mode 0: fp32 out + bias (proj). mode 1: scatter q(QSCALE)/k/v fp16.
__global__ __launch_bounds__(GTHREADS, 1) void gemm_f16_kernel(
    const __half* __restrict__ Ap, const __half* __restrict__ Bw,
    const float* __restrict__ bias, float* __restrict__ C,
    __half* __restrict__ qq, __half* __restrict__ kk, __half* __restrict__ vv,
    int M, int N, int K, int mode)
{
    extern __shared__ char smg[];
    const uint32_t sb = smem_u32(smg);
    const int tid  = threadIdx.x;
    const int wid  = tid >> 5;
    const int lane = tid & 31;
    const int wm   = wid & 1;           // 2 m-slots of 64
    const int wn   = wid >> 1;          // 8 n-slots of 32
    const int n0   = blockIdx.x * BN;
    const int m0   = blockIdx.y * BM;
    const int NC   = K / BKc;

    auto issue = [&](int c) {
        const uint32_t sa = sb + (uint32_t)(c & 1) * STAGE;
        const int k0 = c * BKc;
#pragma unroll
        for (int r = 0; r < 2; r++) {            // A: 1024 16B chunks
            int idx = tid + r * GTHREADS;
            int row = idx >> 3, ch = idx & 7;
            CP16(sa + SWZ(row, ch), Ap + (size_t)(m0 + row) * K + k0 + ch * 8);
        }
#pragma unroll
        for (int r = 0; r < 4; r++) {            // B: 2048 16B chunks
            int idx = tid + r * GTHREADS;
            int row = idx >> 5, ch = idx & 31;
            CP16(sa + A_BYTES + bswz(row, ch * 8),
                 Bw + (size_t)(k0 + row) * N + n0 + ch * 8);
        }
        CP_COMMIT();
    };

    float acc[4][4][4];
#pragma unroll
    for (int i = 0; i < 4; i++)
#pragma unroll
        for (int j = 0; j < 4; j++)
#pragma unroll
            for (int q = 0; q < 4; q++) acc[i][j][q] = 0.f;

    issue(0);
    for (int c = 0; c < NC; c++) {
        CP_WAITG(0);
        __syncthreads();
        if (c + 1 < NC) issue(c + 1);

        const uint32_t sa  = sb + (uint32_t)(c & 1) * STAGE;
        const uint32_t sbw = sa + A_BYTES;

#pragma unroll
        for (int s = 0; s < 4; s++) {             // 4 k16-steps per chunk
            uint32_t ah[4][4];
            uint32_t bw[4][2];
#pragma unroll
            for (int t = 0; t < 4; t++) {
                int row = wm * 64 + t * 16 + (lane & 15);
                ldsm_x4(ah[t], sa + SWZ(row, 2 * s + (lane >> 4)));
            }
#pragma unroll
            for (int p = 0; p < 2; p++) {
                int row  = s * 16 + (lane & 15);
                int ncol = wn * 32 + p * 16 + ((lane >> 4) << 3);
                uint32_t r[4];
                ldsm_x4_t(r, sbw + bswz(row, ncol));
                bw[2*p][0]   = r[0]; bw[2*p][1]   = r[1];
                bw[2*p+1][0] = r[2]; bw[2*p+1][1] = r[3];
            }
#pragma unroll
            for (int t = 0; t < 4; t++)
#pragma unroll
                for (int nn = 0; nn < 4; nn++)
                    mma_f16(acc[t][nn], ah[t], bw[nn][0], bw[nn][1]);
        }
    }

    const int grow = lane >> 2;
    const int gcol = (lane & 3) * 2;

    if (mode == 0) {
#pragma unroll
        for (int nn = 0; nn < 4; nn++) {
            int col = n0 + wn * 32 + nn * 8 + gcol;
            float2 bv = *(const float2*)&bias[col];
#pragma unroll
            for (int t = 0; t < 4; t++) {
                int row0 = m0 + wm * 64 + t * 16 + grow;
                float2 o0 = {acc[t][nn][0] + bv.x, acc[t][nn][1] + bv.y};
                float2 o1 = {acc[t][nn][2] + bv.x, acc[t][nn][3] + bv.y};
                *(float2*)&C[(size_t)row0 * N + col] = o0;
                *(float2*)&C[(size_t)(row0 + 8) * N + col] = o1;
            }
        }
    } else {
        // scatter to [B][H][S][64] plain fp16; q pre-scaled by QSCALE
        const int colb = n0 + wn * 32;   // 256-tiles never straddle q/k/v bounds
        const int t3 = colb >> 10;       // 0=q 1=k 2=v (warp-uniform)
        const int hh = (colb & 1023) >> 6;
        const int bidx = m0 >> 11;
        __half* dst = (t3 == 0) ? qq : (t3 == 1) ? kk : vv;
        const float sc = (t3 == 0) ? QSCALE : 1.f;
#pragma unroll
        for (int nn = 0; nn < 4; nn++) {
            int col = colb + nn * 8 + gcol;
            int d = col & 63;
            float2 bv = *(const float2*)&bias[col];
#pragma unroll
            for (int t = 0; t < 4; t++) {
                int row0 = m0 + wm * 64 + t * 16 + grow;
                int s = row0 & 2047;
                size_t base  = ((size_t)(bidx * Hn + hh) * Sn + s) * 64 + d;
                size_t base8 = base + 8 * 64;
                float vx = (acc[t][nn][0] + bv.x) * sc, vy = (acc[t][nn][1] + bv.y) * sc;
                float wx = (acc[t][nn][2] + bv.x) * sc, wy = (acc[t][nn][3] + bv.y) * sc;
                *(uint32_t*)&dst[base]  = pack_f16(vx, vy);
                *(uint32_t*)&dst[base8] = pack_f16(wx, wy);
            }
        }
    }
}

// ---------------------------------------------------------------------------
// Tensor-core flash attention, plain fp16, exp2 softmax, KV PAIR pipeline.
// CTA = 128 q rows of one (b,h); 8 warps x 16 rows; two 64-key tiles per
// barrier (nkt = 2qt+2 is always even). smem: Q 16KB + 4 x 16KB KV = 80KB.
// ---------------------------------------------------------------------------
#define ASMEM (16384 + 4 * 16384)   // 81920

__global__ __launch_bounds__(256, 2) void attn_mma_kernel(
    const __half* __restrict__ Qp,
    const __half* __restrict__ Kp, const __half* __restrict__ Vp,
    __half* __restrict__ outp)
{
    extern __shared__ char sma[];
    const uint32_t sb = smem_u32(sma);
    const uint32_t sQ = sb;
    const int tid = threadIdx.x, wid = tid >> 5, lane = tid & 31;
    const int qt = (gridDim.x - 1) - blockIdx.x;    // heavy tiles first
    const int h = blockIdx.y, b = blockIdx.z;
    const int q0 = qt * 128;
    const size_t head = ((size_t)(b * Hn + h)) * Sn * 64;

    // Q tile: group 0
    for (int i = tid; i < 1024; i += 256) {
        int row = i >> 3, c = i & 7;
        CP16(sQ + SWZ(row, c), Qp + head + (size_t)(q0 + row) * 64 + c * 8);
    }
    CP_COMMIT();

    // issue one PAIR of KV tiles (tiles 2p, 2p+1) as a single commit group
    auto issue_pair = [&](int p) {
#pragma unroll
        for (int half = 0; half < 2; half++) {
            int kt = 2 * p + half;
            uint32_t st = sb + 16384 + (uint32_t)(kt & 3) * 16384;
            const int k0 = kt * 64;
            for (int i = tid; i < 512; i += 256) {
                int row = i >> 3, c = i & 7;
                uint32_t d = SWZ(row, c);
                size_t g = head + (size_t)(k0 + row) * 64 + c * 8;
                CP16(st + d,        Kp + g);
                CP16(st + 8192 + d, Vp + g);
            }
        }
        CP_COMMIT();
    };

    const int np = qt + 1;     // number of KV pairs (nkt = 2*np)
    issue_pair(0);
    CP_WAITG(1);               // Q (group 0) complete
    __syncthreads();

    const int qr      = wid * 16 + (lane & 15);
    const int qc_add  = (lane >> 4);
    const int kr_base = ((lane >> 4) << 3) + (lane & 7);
    const int kc_add  = ((lane >> 3) & 1);
    const int vr      = (lane & 15);

    // hoist Q fragments to registers
    uint32_t qhr[4][4];
#pragma unroll
    for (int ks = 0; ks < 4; ks++)
        ldsm_x4(qhr[ks], sQ + SWZ(qr, 2 * ks + qc_add));

    float oacc[8][4];
#pragma unroll
    for (int j = 0; j < 8; j++)
#pragma unroll
        for (int q = 0; q < 4; q++) oacc[j][q] = 0.f;
    float m[2] = {-1e30f, -1e30f}, l[2] = {0.f, 0.f};

    for (int p = 0; p < np; p++) {
        CP_WAITG(0);           // pair p landed (issued one full pair-compute ago)
        __syncthreads();       // visibility + stage-pair (p+1)&1 reuse guard
        if (p + 1 < np) issue_pair(p + 1);

#pragma unroll
        for (int half = 0; half < 2; half++) {
            const int c = 2 * p + half;
            const uint32_t stK = sb + 16384 + (uint32_t)(c & 3) * 16384;
            const uint32_t stV = stK + 8192;
            const int k0 = c * 64;

            // ---- S = Q K^T ----
            float sacc[8][4];
#pragma unroll
            for (int j = 0; j < 8; j++)
#pragma unroll
                for (int q = 0; q < 4; q++) sacc[j][q] = 0.f;

#pragma unroll
            for (int ks = 0; ks < 4; ks++) {
#pragma unroll
                for (int kg = 0; kg < 4; kg++) {
                    uint32_t kh4[4];
                    ldsm_x4(kh4, stK + SWZ(kg * 16 + kr_base, 2 * ks + kc_add));
                    mma_f16(sacc[2*kg],   qhr[ks], kh4[0], kh4[1]);
                    mma_f16(sacc[2*kg+1], qhr[ks], kh4[2], kh4[3]);
                }
            }

            // ---- causal mask ----
            const int r0g = q0 + wid * 16 + (lane >> 2);
            if (k0 + 63 > q0 + wid * 16) {
#pragma unroll
                for (int j = 0; j < 8; j++) {
                    int key = k0 + 8 * j + (lane & 3) * 2;
                    if (key     > r0g)     sacc[j][0] = -1e30f;
                    if (key + 1 > r0g)     sacc[j][1] = -1e30f;
                    if (key     > r0g + 8) sacc[j][2] = -1e30f;
                    if (key + 1 > r0g + 8) sacc[j][3] = -1e30f;
                }
            }

            // ---- online softmax (exp2 domain) per row-group ----
#pragma unroll
            for (int rg = 0; rg < 2; rg++) {
                float tm = -1e30f;
#pragma unroll
                for (int j = 0; j < 8; j++)
                    tm = fmaxf(tm, fmaxf(sacc[j][2*rg], sacc[j][2*rg+1]));
                tm = fmaxf(tm, __shfl_xor_sync(0xffffffffu, tm, 1));
                tm = fmaxf(tm, __shfl_xor_sync(0xffffffffu, tm, 2));
                float mnew = fmaxf(m[rg], tm);
                float corr = ex2(m[rg] - mnew);
                m[rg] = mnew;
                float rs = 0.f;
#pragma unroll
                for (int j = 0; j < 8; j++) {
                    float e0 = ex2(sacc[j][2*rg]   - mnew);
                    float e1 = ex2(sacc[j][2*rg+1] - mnew);
                    sacc[j][2*rg] = e0; sacc[j][2*rg+1] = e1;
                    rs += e0 + e1;
                }
                rs += __shfl_xor_sync(0xffffffffu, rs, 1);
                rs += __shfl_xor_sync(0xffffffffu, rs, 2);
                l[rg] = l[rg] * corr + rs;
#pragma unroll
                for (int j = 0; j < 8; j++) {
                    oacc[j][2*rg]   *= corr;
                    oacc[j][2*rg+1] *= corr;
                }
            }

            // ---- O += P V ----
#pragma unroll
            for (int t = 0; t < 4; t++) {
                uint32_t phi[4];
                phi[0] = pack_f16(sacc[2*t][0],   sacc[2*t][1]);
                phi[1] = pack_f16(sacc[2*t][2],   sacc[2*t][3]);
                phi[2] = pack_f16(sacc[2*t+1][0], sacc[2*t+1][1]);
                phi[3] = pack_f16(sacc[2*t+1][2], sacc[2*t+1][3]);
                int vrow = t * 16 + vr;
#pragma unroll
                for (int pp = 0; pp < 4; pp++) {
                    uint32_t vh4[4];
                    ldsm_x4_t(vh4, stV + SWZ(vrow, 2 * pp + qc_add));
                    mma_f16(oacc[2*pp],   phi, vh4[0], vh4[1]);
                    mma_f16(oacc[2*pp+1], phi, vh4[2], vh4[3]);
                }
            }
        }
    }

    // ---- normalize + plain fp16 store to [row=(b,s)][h*64+d] ----
    const float inv0 = 1.f / l[0], inv1 = 1.f / l[1];
    const int s0 = q0 + wid * 16 + (lane >> 2);
#pragma unroll
    for (int j = 0; j < 8; j++) {
        int dcol = h * 64 + 8 * j + (lane & 3) * 2;
        size_t i0 = (size_t)(b * Sn + s0) * HHD + dcol;
        size_t i1 = i0 + (size_t)8 * HHD;
        *(uint32_t*)&outp[i0] = pack_f16(oacc[j][0] * inv0, oacc[j][1] * inv0);
        *(uint32_t*)&outp[i1] = pack_f16(oacc[j][2] * inv1, oacc[j][3] * inv1);
    }
}

// ---------------------------------------------------------------------------
extern "C" void kernel_launch(void* const* d_in, const int* in_sizes, int n_in,
                              void* d_out, int out_size)
{
    const float* x      = (const float*)d_in[0];
    const float* w_qkv  = (const float*)d_in[1];
    const float* b_qkv  = (const float*)d_in[2];
    const float* w_proj = (const float*)d_in[3];
    const float* b_proj = (const float*)d_in[4];
    float* out = (float*)d_out;

    __half *xh, *wq, *wp, *att, *qq, *kk, *vv;
    cudaGetSymbolAddress((void**)&xh, g_x);
    cudaGetSymbolAddress((void**)&wq, g_wqkv);
    cudaGetSymbolAddress((void**)&wp, g_wproj);
    cudaGetSymbolAddress((void**)&att, g_att);
    cudaGetSymbolAddress((void**)&qq, g_q);
    cudaGetSymbolAddress((void**)&kk, g_k);
    cudaGetSymbolAddress((void**)&vv, g_v);

    cudaFuncSetAttribute(gemm_f16_kernel,
                         cudaFuncAttributeMaxDynamicSharedMemorySize, SMEM_G);
    cudaFuncSetAttribute(attn_mma_kernel,
                         cudaFuncAttributeMaxDynamicSharedMemorySize, ASMEM);

    // fused prep (x + both weights -> plain fp16)
    prep_kernel<<<(NX4 + NW14 + NW24) / 256, 256>>>(x, w_qkv, w_proj, xh, wq, wp);

    // 1) QKV GEMM -> head-major q(QSCALE)/k/v plain fp16
    gemm_f16_kernel<<<dim3(QKVROW / BN, Mrows / BM), GTHREADS, SMEM_G>>>(
        xh, wq, b_qkv, nullptr, qq, kk, vv, Mrows, QKVROW, Dn, 1);

    // 2) tensor-core causal flash attention -> att plain fp16
    attn_mma_kernel<<<dim3(Sn / 128, Hn, Bn), 256, ASMEM>>>(qq, kk, vv, att);

    // 3) proj GEMM -> fp32 out + bias
    gemm_f16_kernel<<<dim3(Dn / BN, Mrows / BM), GTHREADS, SMEM_G>>>(
        att, wp, b_proj, out, nullptr, nullptr, nullptr, Mrows, Dn, HHD, 0);
}

// round 11
// speedup vs baseline: 1.0914x; 1.0914x over previous
#include <cuda_runtime.h>
#include <cuda_fp16.h>
#include <math.h>
#include <stdint.h>

// Problem constants
#define Bn   4
#define Sn   2048
#define Dn   1024
#define Hn   16
#define HDn  64
#define HHD  (Hn*HDn)      // 1024
#define QKVROW (3*HHD)     // 3072
#define Mrows (Bn*Sn)      // 8192

// Q pre-scale: rsqrt(64) * log2(e)  (softmax done in exp2 domain)
#define QSCALE 0.1803368801111f

// ---------------- scratch (allocation-free device globals) ----------------
__device__ __align__(128) __half g_x[(size_t)Mrows * Dn];
__device__ __align__(128) __half g_wqkv[(size_t)Dn * QKVROW];   // [K][N] fp16
__device__ __align__(128) __half g_wproj[(size_t)HHD * Dn];     // [K][N] fp16
__device__ __align__(128) __half g_q[(size_t)Bn * Hn * Sn * HDn];
__device__ __align__(128) __half g_k[(size_t)Bn * Hn * Sn * HDn];
__device__ __align__(128) __half g_v[(size_t)Bn * Hn * Sn * HDn];
__device__ __align__(128) __half g_att[(size_t)Mrows * HHD];

// ---------------- PTX helpers ----------------
__device__ __forceinline__ uint32_t smem_u32(const void* p) {
    uint32_t a;
    asm("{ .reg .u64 t; cvta.to.shared.u64 t, %1; cvt.u32.u64 %0, t; }" : "=r"(a) : "l"(p));
    return a;
}
#define CP16(s, g) asm volatile("cp.async.cg.shared.global [%0], [%1], 16;" :: "r"(s), "l"(g))
#define CP_COMMIT() asm volatile("cp.async.commit_group;" ::: "memory")
#define CP_WAITG(n) asm volatile("cp.async.wait_group %0;" :: "n"(n) : "memory")

__device__ __forceinline__ void ldsm_x4(uint32_t (&r)[4], uint32_t addr) {
    asm volatile("ldmatrix.sync.aligned.m8n8.x4.shared.b16 {%0,%1,%2,%3}, [%4];"
                 : "=r"(r[0]), "=r"(r[1]), "=r"(r[2]), "=r"(r[3]) : "r"(addr));
}
__device__ __forceinline__ void ldsm_x4_t(uint32_t (&r)[4], uint32_t addr) {
    asm volatile("ldmatrix.sync.aligned.m8n8.x4.trans.shared.b16 {%0,%1,%2,%3}, [%4];"
                 : "=r"(r[0]), "=r"(r[1]), "=r"(r[2]), "=r"(r[3]) : "r"(addr));
}
__device__ __forceinline__ void mma_f16(float (&c)[4], const uint32_t (&a)[4],
                                        uint32_t b0, uint32_t b1) {
    asm volatile(
        "mma.sync.aligned.m16n8k16.row.col.f32.f16.f16.f32 "
        "{%0,%1,%2,%3}, {%4,%5,%6,%7}, {%8,%9}, {%0,%1,%2,%3};"
        : "+f"(c[0]), "+f"(c[1]), "+f"(c[2]), "+f"(c[3])
        : "r"(a[0]), "r"(a[1]), "r"(a[2]), "r"(a[3]), "r"(b0), "r"(b1));
}
__device__ __forceinline__ uint32_t pack_f16(float lo, float hi) {
    uint32_t r;
    asm("cvt.rn.f16x2.f32 %0, %1, %2;" : "=r"(r) : "f"(hi), "f"(lo));
    return r;
}
__device__ __forceinline__ float ex2(float x) {
    float r;
    asm("ex2.approx.ftz.f32 %0, %1;" : "=f"(r) : "f"(x));
    return r;
}
__device__ __forceinline__ uint32_t ex2_h2(uint32_t x) {
    uint32_t r;
    asm("ex2.approx.f16x2 %0, %1;" : "=r"(r) : "r"(x));
    return r;
}
__device__ __forceinline__ uint32_t hadd2(uint32_t a, uint32_t b) {
    uint32_t r;
    asm("add.rn.f16x2 %0, %1, %2;" : "=r"(r) : "r"(a), "r"(b));
    return r;
}
// XOR-swizzled smem offset for 128B rows (byte offset); c = 16B chunk 0..7
#define SWZ(row, c) ((uint32_t)((row) * 128 + (((c) ^ ((row) & 7)) << 4)))
// 256B-row B tile: per-128B-half XOR swizzle; ncol = fp16 column 0..127
__device__ __forceinline__ uint32_t bswz(int row, int ncol) {
    int ch = ncol >> 3;
    return (uint32_t)(row * 256 + ((ch >> 3) << 7) + (((ch & 7) ^ (row & 7)) << 4));
}

// ---------------- fused prep kernel ----------------
#define NX4  ((Mrows * Dn) / 4)
#define NW14 ((Dn * QKVROW) / 4)
#define NW24 ((HHD * Dn) / 4)

__global__ __launch_bounds__(256) void prep_kernel(
    const float* __restrict__ x, const float* __restrict__ wq_in,
    const float* __restrict__ wp_in,
    __half* __restrict__ xh, __half* __restrict__ wq, __half* __restrict__ wp)
{
    int i = blockIdx.x * 256 + threadIdx.x;
    const float* src;
    __half* dst;
    int j;
    if (i < NX4) {
        src = x; dst = xh; j = i;
    } else if (i < NX4 + NW14) {
        src = wq_in; dst = wq; j = i - NX4;
    } else {
        src = wp_in; dst = wp; j = i - NX4 - NW14;
    }
    float4 v = ((const float4*)src)[j];
    ((uint32_t*)dst)[j * 2 + 0] = pack_f16(v.x, v.y);
    ((uint32_t*)dst)[j * 2 + 1] = pack_f16(v.z, v.w);
}

// ---------------- plain fp16 GEMM: 256 threads, 128x128 tile, BK=64 ----------
#define BM 128
#define BN 128
#define BKc 64
#define A_BYTES (BM * 128)              // 16384
#define B_BYTES (BKc * 256)             // 16384
#define STAGE   (A_BYTES + B_BYTES)     // 32768
#define SMEM_G  (2 * STAGE)             // 65536

// mode 0: fp32 out + bias (proj). mode 1: scatter q(QSCALE)/k/v fp16.
__global__ __launch_bounds__(256, 2) void gemm_f16_kernel(
    const __half* __restrict__ Ap, const __half* __restrict__ Bw,
    const float* __restrict__ bias, float* __restrict__ C,
    __half* __restrict__ qq, __half* __restrict__ kk, __half* __restrict__ vv,
    int M, int N, int K, int mode)
{
    extern __shared__ char smg[];
    const uint32_t sb = smem_u32(smg);
    const int tid  = threadIdx.x;
    const int wid  = tid >> 5;
    const int lane = tid & 31;
    const int wm   = wid & 1;
    const int wn   = wid >> 1;
    const int n0   = blockIdx.x * BN;
    const int m0   = blockIdx.y * BM;
    const int NC   = K / BKc;           // 16

    auto issue = [&](int c) {
        const uint32_t sa = sb + (uint32_t)(c & 1) * STAGE;
        const int k0 = c * BKc;
#pragma unroll
        for (int r = 0; r < 4; r++) {            // A: 1024 16B chunks
            int idx = tid + r * 256;
            int row = idx >> 3, ch = idx & 7;
            CP16(sa + SWZ(row, ch), Ap + (size_t)(m0 + row) * K + k0 + ch * 8);
        }
#pragma unroll
        for (int r = 0; r < 4; r++) {            // B: 1024 16B chunks
            int idx = tid + r * 256;
            int row = idx >> 4, ch = idx & 15;
            CP16(sa + A_BYTES + bswz(row, ch * 8),
                 Bw + (size_t)(k0 + row) * N + n0 + ch * 8);
        }
        CP_COMMIT();
    };

    float acc[4][4][4];
#pragma unroll
    for (int i = 0; i < 4; i++)
#pragma unroll
        for (int j = 0; j < 4; j++)
#pragma unroll
            for (int q = 0; q < 4; q++) acc[i][j][q] = 0.f;

    issue(0);
    for (int c = 0; c < NC; c++) {
        CP_WAITG(0);
        __syncthreads();
        if (c + 1 < NC) issue(c + 1);

        const uint32_t sa  = sb + (uint32_t)(c & 1) * STAGE;
        const uint32_t sbw = sa + A_BYTES;

#pragma unroll
        for (int s = 0; s < 4; s++) {             // 4 k16-steps per chunk
            uint32_t ah[4][4];
            uint32_t bw[4][2];
#pragma unroll
            for (int t = 0; t < 4; t++) {
                int row = wm * 64 + t * 16 + (lane & 15);
                ldsm_x4(ah[t], sa + SWZ(row, 2 * s + (lane >> 4)));
            }
#pragma unroll
            for (int p = 0; p < 2; p++) {
                int row  = s * 16 + (lane & 15);
                int ncol = wn * 32 + p * 16 + ((lane >> 4) << 3);
                uint32_t r[4];
                ldsm_x4_t(r, sbw + bswz(row, ncol));
                bw[2*p][0]   = r[0]; bw[2*p][1]   = r[1];
                bw[2*p+1][0] = r[2]; bw[2*p+1][1] = r[3];
            }
#pragma unroll
            for (int t = 0; t < 4; t++)
#pragma unroll
                for (int nn = 0; nn < 4; nn++)
                    mma_f16(acc[t][nn], ah[t], bw[nn][0], bw[nn][1]);
        }
    }

    const int grow = lane >> 2;
    const int gcol = (lane & 3) * 2;

    if (mode == 0) {
#pragma unroll
        for (int nn = 0; nn < 4; nn++) {
            int col = n0 + wn * 32 + nn * 8 + gcol;
            float2 bv = *(const float2*)&bias[col];
#pragma unroll
            for (int t = 0; t < 4; t++) {
                int row0 = m0 + wm * 64 + t * 16 + grow;
                float2 o0 = {acc[t][nn][0] + bv.x, acc[t][nn][1] + bv.y};
                float2 o1 = {acc[t][nn][2] + bv.x, acc[t][nn][3] + bv.y};
                *(float2*)&C[(size_t)row0 * N + col] = o0;
                *(float2*)&C[(size_t)(row0 + 8) * N + col] = o1;
            }
        }
    } else {
        const int colb = n0 + wn * 32;
        const int t3 = colb >> 10;               // 0=q 1=k 2=v (warp-uniform)
        const int hh = (colb & 1023) >> 6;
        const int bidx = m0 >> 11;
        __half* dst = (t3 == 0) ? qq : (t3 == 1) ? kk : vv;
        const float sc = (t3 == 0) ? QSCALE : 1.f;
#pragma unroll
        for (int nn = 0; nn < 4; nn++) {
            int col = colb + nn * 8 + gcol;
            int d = col & 63;
            float2 bv = *(const float2*)&bias[col];
#pragma unroll
            for (int t = 0; t < 4; t++) {
                int row0 = m0 + wm * 64 + t * 16 + grow;
                int s = row0 & 2047;
                size_t base  = ((size_t)(bidx * Hn + hh) * Sn + s) * 64 + d;
                size_t base8 = base + 8 * 64;
                float vx = (acc[t][nn][0] + bv.x) * sc, vy = (acc[t][nn][1] + bv.y) * sc;
                float wx = (acc[t][nn][2] + bv.x) * sc, wy = (acc[t][nn][3] + bv.y) * sc;
                *(uint32_t*)&dst[base]  = pack_f16(vx, vy);
                *(uint32_t*)&dst[base8] = pack_f16(wx, wy);
            }
        }
    }
}

// ---------------------------------------------------------------------------
// Tensor-core flash attention, plain fp16, f16x2 exp2 softmax, 4-stage KV.
// CTA = 128 q rows of one (b,h); 8 warps x 16 rows; 64-key tiles.
// smem: Q 16KB + 4 stages x (K 8KB + V 8KB) = 80KB.
// ---------------------------------------------------------------------------
#define KVSTAGES 4
#define ASMEM (16384 + KVSTAGES * 16384)   // 81920

__global__ __launch_bounds__(256, 2) void attn_mma_kernel(
    const __half* __restrict__ Qp,
    const __half* __restrict__ Kp, const __half* __restrict__ Vp,
    __half* __restrict__ outp)
{
    extern __shared__ char sma[];
    const uint32_t sb = smem_u32(sma);
    const uint32_t sQ = sb;
    const int tid = threadIdx.x, wid = tid >> 5, lane = tid & 31;
    const int qt = (gridDim.x - 1) - blockIdx.x;    // heavy tiles first
    const int h = blockIdx.y, b = blockIdx.z;
    const int q0 = qt * 128;
    const size_t head = ((size_t)(b * Hn + h)) * Sn * 64;

    // Q tile: group 0
    for (int i = tid; i < 1024; i += 256) {
        int row = i >> 3, c = i & 7;
        CP16(sQ + SWZ(row, c), Qp + head + (size_t)(q0 + row) * 64 + c * 8);
    }
    CP_COMMIT();

    auto issue_kv = [&](int kt) {
        uint32_t st = sb + 16384 + (uint32_t)(kt & (KVSTAGES - 1)) * 16384;
        const int k0 = kt * 64;
        for (int i = tid; i < 512; i += 256) {
            int row = i >> 3, c = i & 7;
            uint32_t d = SWZ(row, c);
            size_t g = head + (size_t)(k0 + row) * 64 + c * 8;
            CP16(st + d,        Kp + g);
            CP16(st + 8192 + d, Vp + g);
        }
        CP_COMMIT();
    };

    const int nkt = 2 * qt + 2;
#pragma unroll
    for (int kt = 0; kt < 3; kt++) {
        if (kt < nkt) issue_kv(kt); else CP_COMMIT();
    }
    CP_WAITG(3);          // Q (group 0) complete
    __syncthreads();

    const int qr      = wid * 16 + (lane & 15);
    const int qc_add  = (lane >> 4);
    const int kr_base = ((lane >> 4) << 3) + (lane & 7);
    const int kc_add  = ((lane >> 3) & 1);
    const int vr      = (lane & 15);

    // hoist Q fragments to registers
    uint32_t qhr[4][4];
#pragma unroll
    for (int ks = 0; ks < 4; ks++)
        ldsm_x4(qhr[ks], sQ + SWZ(qr, 2 * ks + qc_add));

    float oacc[8][4];
#pragma unroll
    for (int j = 0; j < 8; j++)
#pragma unroll
        for (int q = 0; q < 4; q++) oacc[j][q] = 0.f;
    float m[2] = {-1e30f, -1e30f};
    float l[2] = {0.f, 0.f};           // lane-partial; reduced at the end

    for (int c = 0; c < nkt; c++) {
        CP_WAITG(2);
        __syncthreads();
        if (c + 3 < nkt) issue_kv(c + 3); else CP_COMMIT();

        const uint32_t stK = sb + 16384 + (uint32_t)(c & (KVSTAGES - 1)) * 16384;
        const uint32_t stV = stK + 8192;
        const int k0 = c * 64;

        // ---- S = Q K^T ----
        float sacc[8][4];
#pragma unroll
        for (int j = 0; j < 8; j++)
#pragma unroll
            for (int q = 0; q < 4; q++) sacc[j][q] = 0.f;

#pragma unroll
        for (int ks = 0; ks < 4; ks++) {
#pragma unroll
            for (int kg = 0; kg < 4; kg++) {
                uint32_t kh4[4];
                ldsm_x4(kh4, stK + SWZ(kg * 16 + kr_base, 2 * ks + kc_add));
                mma_f16(sacc[2*kg],   qhr[ks], kh4[0], kh4[1]);
                mma_f16(sacc[2*kg+1], qhr[ks], kh4[2], kh4[3]);
            }
        }

        // ---- causal mask ----
        const int r0g = q0 + wid * 16 + (lane >> 2);
        if (k0 + 63 > q0 + wid * 16) {
#pragma unroll
            for (int j = 0; j < 8; j++) {
                int key = k0 + 8 * j + (lane & 3) * 2;
                if (key     > r0g)     sacc[j][0] = -1e30f;
                if (key + 1 > r0g)     sacc[j][1] = -1e30f;
                if (key     > r0g + 8) sacc[j][2] = -1e30f;
                if (key + 1 > r0g + 8) sacc[j][3] = -1e30f;
            }
        }

        // ---- online softmax (exp2 domain, f16x2 exp) per row-group ----
        uint32_t pp0[8], pp1[8];       // packed p: rg0 / rg1
#pragma unroll
        for (int rg = 0; rg < 2; rg++) {
            float tm = -1e30f;
#pragma unroll
            for (int j = 0; j < 8; j++)
                tm = fmaxf(tm, fmaxf(sacc[j][2*rg], sacc[j][2*rg+1]));
            tm = fmaxf(tm, __shfl_xor_sync(0xffffffffu, tm, 1));
            tm = fmaxf(tm, __shfl_xor_sync(0xffffffffu, tm, 2));
            float mnew = fmaxf(m[rg], tm);
            float corr = ex2(m[rg] - mnew);
            m[rg] = mnew;
            uint32_t rs2 = 0u;
#pragma unroll
            for (int j = 0; j < 8; j++) {
                // subtract in fp32 (dominant-p precision), pack, packed ex2
                uint32_t d = pack_f16(sacc[j][2*rg] - mnew, sacc[j][2*rg+1] - mnew);
                uint32_t e = ex2_h2(d);
                if (rg == 0) pp0[j] = e; else pp1[j] = e;
                rs2 = hadd2(rs2, e);
            }
            __half2 h2 = *(__half2*)&rs2;
            float rs = __low2float(h2) + __high2float(h2);
            l[rg] = l[rg] * corr + rs;
#pragma unroll
            for (int j = 0; j < 8; j++) {
                oacc[j][2*rg]   *= corr;
                oacc[j][2*rg+1] *= corr;
            }
        }

        // ---- O += P V (P already packed f16) ----
#pragma unroll
        for (int t = 0; t < 4; t++) {
            uint32_t phi[4];
            phi[0] = pp0[2*t];
            phi[1] = pp1[2*t];
            phi[2] = pp0[2*t+1];
            phi[3] = pp1[2*t+1];
            int vrow = t * 16 + vr;
#pragma unroll
            for (int p = 0; p < 4; p++) {
                uint32_t vh4[4];
                ldsm_x4_t(vh4, stV + SWZ(vrow, 2 * p + qc_add));
                mma_f16(oacc[2*p],   phi, vh4[0], vh4[1]);
                mma_f16(oacc[2*p+1], phi, vh4[2], vh4[3]);
            }
        }
    }

    // ---- final l reduction across the 4 lanes of each row ----
#pragma unroll
    for (int rg = 0; rg < 2; rg++) {
        l[rg] += __shfl_xor_sync(0xffffffffu, l[rg], 1);
        l[rg] += __shfl_xor_sync(0xffffffffu, l[rg], 2);
    }

    // ---- normalize + plain fp16 store to [row=(b,s)][h*64+d] ----
    const float inv0 = 1.f / l[0], inv1 = 1.f / l[1];
    const int s0 = q0 + wid * 16 + (lane >> 2);
#pragma unroll
    for (int j = 0; j < 8; j++) {
        int dcol = h * 64 + 8 * j + (lane & 3) * 2;
        size_t i0 = (size_t)(b * Sn + s0) * HHD + dcol;
        size_t i1 = i0 + (size_t)8 * HHD;
        *(uint32_t*)&outp[i0] = pack_f16(oacc[j][0] * inv0, oacc[j][1] * inv0);
        *(uint32_t*)&outp[i1] = pack_f16(oacc[j][2] * inv1, oacc[j][3] * inv1);
    }
}

// ---------------------------------------------------------------------------
extern "C" void kernel_launch(void* const* d_in, const int* in_sizes, int n_in,
                              void* d_out, int out_size)
{
    const float* x      = (const float*)d_in[0];
    const float* w_qkv  = (const float*)d_in[1];
    const float* b_qkv  = (const float*)d_in[2];
    const float* w_proj = (const float*)d_in[3];
    const float* b_proj = (const float*)d_in[4];
    float* out = (float*)d_out;

    __half *xh, *wq, *wp, *att, *qq, *kk, *vv;
    cudaGetSymbolAddress((void**)&xh, g_x);
    cudaGetSymbolAddress((void**)&wq, g_wqkv);
    cudaGetSymbolAddress((void**)&wp, g_wproj);
    cudaGetSymbolAddress((void**)&att, g_att);
    cudaGetSymbolAddress((void**)&qq, g_q);
    cudaGetSymbolAddress((void**)&kk, g_k);
    cudaGetSymbolAddress((void**)&vv, g_v);

    cudaFuncSetAttribute(gemm_f16_kernel,
                         cudaFuncAttributeMaxDynamicSharedMemorySize, SMEM_G);
    cudaFuncSetAttribute(attn_mma_kernel,
                         cudaFuncAttributeMaxDynamicSharedMemorySize, ASMEM);

    // fused prep (x + both weights -> plain fp16)
    prep_kernel<<<(NX4 + NW14 + NW24) / 256, 256>>>(x, w_qkv, w_proj, xh, wq, wp);

    // 1) QKV GEMM -> head-major q(QSCALE)/k/v plain fp16
    gemm_f16_kernel<<<dim3(QKVROW / BN, Mrows / BM), 256, SMEM_G>>>(
        xh, wq, b_qkv, nullptr, qq, kk, vv, Mrows, QKVROW, Dn, 1);

    // 2) tensor-core causal flash attention -> att plain fp16
    attn_mma_kernel<<<dim3(Sn / 128, Hn, Bn), 256, ASMEM>>>(qq, kk, vv, att);

    // 3) proj GEMM -> fp32 out + bias
    gemm_f16_kernel<<<dim3(Dn / BN, Mrows / BM), 256, SMEM_G>>>(
        att, wp, b_proj, out, nullptr, nullptr, nullptr, Mrows, Dn, HHD, 0);
}

// round 12
// speedup vs baseline: 1.1037x; 1.0113x over previous
#include <cuda_runtime.h>
#include <cuda_fp16.h>
#include <math.h>
#include <stdint.h>

// Problem constants
#define Bn   4
#define Sn   2048
#define Dn   1024
#define Hn   16
#define HDn  64
#define HHD  (Hn*HDn)      // 1024
#define QKVROW (3*HHD)     // 3072
#define Mrows (Bn*Sn)      // 8192

// Q pre-scale: rsqrt(64) * log2(e)  (softmax done in exp2 domain)
#define QSCALE 0.1803368801111f

// ---------------- scratch (allocation-free device globals) ----------------
__device__ __align__(128) __half g_x[(size_t)Mrows * Dn];
__device__ __align__(128) __half g_wqkv[(size_t)Dn * QKVROW];   // [K][N] fp16
__device__ __align__(128) __half g_wproj[(size_t)HHD * Dn];     // [K][N] fp16
__device__ __align__(128) __half g_q[(size_t)Bn * Hn * Sn * HDn];
__device__ __align__(128) __half g_k[(size_t)Bn * Hn * Sn * HDn];
__device__ __align__(128) __half g_v[(size_t)Bn * Hn * Sn * HDn];
__device__ __align__(128) __half g_att[(size_t)Mrows * HHD];

// ---------------- PTX helpers ----------------
__device__ __forceinline__ uint32_t smem_u32(const void* p) {
    uint32_t a;
    asm("{ .reg .u64 t; cvta.to.shared.u64 t, %1; cvt.u32.u64 %0, t; }" : "=r"(a) : "l"(p));
    return a;
}
#define CP16(s, g) asm volatile("cp.async.cg.shared.global [%0], [%1], 16;" :: "r"(s), "l"(g))
#define CP_COMMIT() asm volatile("cp.async.commit_group;" ::: "memory")
#define CP_WAITG(n) asm volatile("cp.async.wait_group %0;" :: "n"(n) : "memory")

__device__ __forceinline__ void ldsm_x4(uint32_t (&r)[4], uint32_t addr) {
    asm volatile("ldmatrix.sync.aligned.m8n8.x4.shared.b16 {%0,%1,%2,%3}, [%4];"
                 : "=r"(r[0]), "=r"(r[1]), "=r"(r[2]), "=r"(r[3]) : "r"(addr));
}
__device__ __forceinline__ void ldsm_x4_t(uint32_t (&r)[4], uint32_t addr) {
    asm volatile("ldmatrix.sync.aligned.m8n8.x4.trans.shared.b16 {%0,%1,%2,%3}, [%4];"
                 : "=r"(r[0]), "=r"(r[1]), "=r"(r[2]), "=r"(r[3]) : "r"(addr));
}
__device__ __forceinline__ void mma_f16(float (&c)[4], const uint32_t (&a)[4],
                                        uint32_t b0, uint32_t b1) {
    asm volatile(
        "mma.sync.aligned.m16n8k16.row.col.f32.f16.f16.f32 "
        "{%0,%1,%2,%3}, {%4,%5,%6,%7}, {%8,%9}, {%0,%1,%2,%3};"
        : "+f"(c[0]), "+f"(c[1]), "+f"(c[2]), "+f"(c[3])
        : "r"(a[0]), "r"(a[1]), "r"(a[2]), "r"(a[3]), "r"(b0), "r"(b1));
}
__device__ __forceinline__ uint32_t pack_f16(float lo, float hi) {
    uint32_t r;
    asm("cvt.rn.f16x2.f32 %0, %1, %2;" : "=r"(r) : "f"(hi), "f"(lo));
    return r;
}
__device__ __forceinline__ float ex2(float x) {
    float r;
    asm("ex2.approx.ftz.f32 %0, %1;" : "=f"(r) : "f"(x));
    return r;
}
__device__ __forceinline__ uint32_t ex2_h2(uint32_t x) {
    uint32_t r;
    asm("ex2.approx.f16x2 %0, %1;" : "=r"(r) : "r"(x));
    return r;
}
__device__ __forceinline__ uint32_t hadd2(uint32_t a, uint32_t b) {
    uint32_t r;
    asm("add.rn.f16x2 %0, %1, %2;" : "=r"(r) : "r"(a), "r"(b));
    return r;
}
// XOR-swizzled smem offset for 128B rows (byte offset); c = 16B chunk 0..7
#define SWZ(row, c) ((uint32_t)((row) * 128 + (((c) ^ ((row) & 7)) << 4)))
// 256B-row B tile: per-128B-half XOR swizzle; ncol = fp16 column 0..127
__device__ __forceinline__ uint32_t bswz(int row, int ncol) {
    int ch = ncol >> 3;
    return (uint32_t)(row * 256 + ((ch >> 3) << 7) + (((ch & 7) ^ (row & 7)) << 4));
}

// ---------------- fused prep kernel ----------------
#define NX4  ((Mrows * Dn) / 4)
#define NW14 ((Dn * QKVROW) / 4)
#define NW24 ((HHD * Dn) / 4)

__global__ __launch_bounds__(256) void prep_kernel(
    const float* __restrict__ x, const float* __restrict__ wq_in,
    const float* __restrict__ wp_in,
    __half* __restrict__ xh, __half* __restrict__ wq, __half* __restrict__ wp)
{
    int i = blockIdx.x * 256 + threadIdx.x;
    const float* src;
    __half* dst;
    int j;
    if (i < NX4) {
        src = x; dst = xh; j = i;
    } else if (i < NX4 + NW14) {
        src = wq_in; dst = wq; j = i - NX4;
    } else {
        src = wp_in; dst = wp; j = i - NX4 - NW14;
    }
    float4 v = ((const float4*)src)[j];
    ((uint32_t*)dst)[j * 2 + 0] = pack_f16(v.x, v.y);
    ((uint32_t*)dst)[j * 2 + 1] = pack_f16(v.z, v.w);
}

// ---------------- fp16 GEMM: 128 threads, 4 warps, warp tile 64x64 ----------
// CTA tile 128x128, BK=64, 2 stages. smem reads/chunk drop to 64KB (B frags
// reused by 4 MMAs) -> below the 128B/cyc crossbar budget.
#define BM 128
#define BN 128
#define BKc 64
#define A_BYTES (BM * 128)              // 16384
#define B_BYTES (BKc * 256)             // 16384
#define STAGE   (A_BYTES + B_BYTES)     // 32768
#define SMEM_G  (2 * STAGE)             // 65536
#define GTH 128

// mode 0: fp32 out + bias (proj). mode 1: scatter q(QSCALE)/k/v fp16.
__global__ __launch_bounds__(GTH, 2) void gemm_f16_kernel(
    const __half* __restrict__ Ap, const __half* __restrict__ Bw,
    const float* __restrict__ bias, float* __restrict__ C,
    __half* __restrict__ qq, __half* __restrict__ kk, __half* __restrict__ vv,
    int M, int N, int K, int mode)
{
    extern __shared__ char smg[];
    const uint32_t sb = smem_u32(smg);
    const int tid  = threadIdx.x;
    const int wid  = tid >> 5;
    const int lane = tid & 31;
    const int wm   = wid & 1;           // 2 m-slots of 64
    const int wn   = wid >> 1;          // 2 n-slots of 64
    const int n0   = blockIdx.x * BN;
    const int m0   = blockIdx.y * BM;
    const int NC   = K / BKc;           // 16

    auto issue = [&](int c) {
        const uint32_t sa = sb + (uint32_t)(c & 1) * STAGE;
        const int k0 = c * BKc;
#pragma unroll
        for (int r = 0; r < 8; r++) {            // A: 1024 16B chunks
            int idx = tid + r * GTH;
            int row = idx >> 3, ch = idx & 7;
            CP16(sa + SWZ(row, ch), Ap + (size_t)(m0 + row) * K + k0 + ch * 8);
        }
#pragma unroll
        for (int r = 0; r < 8; r++) {            // B: 1024 16B chunks
            int idx = tid + r * GTH;
            int row = idx >> 4, ch = idx & 15;
            CP16(sa + A_BYTES + bswz(row, ch * 8),
                 Bw + (size_t)(k0 + row) * N + n0 + ch * 8);
        }
        CP_COMMIT();
    };

    float acc[4][8][4];                 // 64x64 warp tile: 4 m-frags x 8 n-frags
#pragma unroll
    for (int i = 0; i < 4; i++)
#pragma unroll
        for (int j = 0; j < 8; j++)
#pragma unroll
            for (int q = 0; q < 4; q++) acc[i][j][q] = 0.f;

    issue(0);
    for (int c = 0; c < NC; c++) {
        CP_WAITG(0);
        __syncthreads();
        if (c + 1 < NC) issue(c + 1);

        const uint32_t sa  = sb + (uint32_t)(c & 1) * STAGE;
        const uint32_t sbw = sa + A_BYTES;

#pragma unroll
        for (int s = 0; s < 4; s++) {             // 4 k16-steps per chunk
            uint32_t ah[4][4];
#pragma unroll
            for (int t = 0; t < 4; t++) {
                int row = wm * 64 + t * 16 + (lane & 15);
                ldsm_x4(ah[t], sa + SWZ(row, 2 * s + (lane >> 4)));
            }
#pragma unroll
            for (int p = 0; p < 4; p++) {         // B frags loaded per-p, 4x reused
                int row  = s * 16 + (lane & 15);
                int ncol = wn * 64 + p * 16 + ((lane >> 4) << 3);
                uint32_t r[4];
                ldsm_x4_t(r, sbw + bswz(row, ncol));
#pragma unroll
                for (int t = 0; t < 4; t++) {
                    mma_f16(acc[t][2*p],   ah[t], r[0], r[1]);
                    mma_f16(acc[t][2*p+1], ah[t], r[2], r[3]);
                }
            }
        }
    }

    const int grow = lane >> 2;
    const int gcol = (lane & 3) * 2;

    if (mode == 0) {
#pragma unroll
        for (int nn = 0; nn < 8; nn++) {
            int col = n0 + wn * 64 + nn * 8 + gcol;
            float2 bv = *(const float2*)&bias[col];
#pragma unroll
            for (int t = 0; t < 4; t++) {
                int row0 = m0 + wm * 64 + t * 16 + grow;
                float2 o0 = {acc[t][nn][0] + bv.x, acc[t][nn][1] + bv.y};
                float2 o1 = {acc[t][nn][2] + bv.x, acc[t][nn][3] + bv.y};
                *(float2*)&C[(size_t)row0 * N + col] = o0;
                *(float2*)&C[(size_t)(row0 + 8) * N + col] = o1;
            }
        }
    } else {
        // scatter to [B][H][S][64] plain fp16; q pre-scaled by QSCALE
        const int colb = n0 + wn * 64;   // 64-wide warp slice = exactly one head
        const int t3 = colb >> 10;       // 0=q 1=k 2=v (warp-uniform)
        const int hh = (colb & 1023) >> 6;
        const int bidx = m0 >> 11;
        __half* dst = (t3 == 0) ? qq : (t3 == 1) ? kk : vv;
        const float sc = (t3 == 0) ? QSCALE : 1.f;
#pragma unroll
        for (int nn = 0; nn < 8; nn++) {
            int col = colb + nn * 8 + gcol;
            int d = col & 63;
            float2 bv = *(const float2*)&bias[col];
#pragma unroll
            for (int t = 0; t < 4; t++) {
                int row0 = m0 + wm * 64 + t * 16 + grow;
                int s = row0 & 2047;
                size_t base  = ((size_t)(bidx * Hn + hh) * Sn + s) * 64 + d;
                size_t base8 = base + 8 * 64;
                float vx = (acc[t][nn][0] + bv.x) * sc, vy = (acc[t][nn][1] + bv.y) * sc;
                float wx = (acc[t][nn][2] + bv.x) * sc, wy = (acc[t][nn][3] + bv.y) * sc;
                *(uint32_t*)&dst[base]  = pack_f16(vx, vy);
                *(uint32_t*)&dst[base8] = pack_f16(wx, wy);
            }
        }
    }
}

// ---------------------------------------------------------------------------
// Tensor-core flash attention, plain fp16, f16x2 exp2 softmax, 4-stage KV.
// (unchanged from R11)
// ---------------------------------------------------------------------------
#define KVSTAGES 4
#define ASMEM (16384 + KVSTAGES * 16384)   // 81920

__global__ __launch_bounds__(256, 2) void attn_mma_kernel(
    const __half* __restrict__ Qp,
    const __half* __restrict__ Kp, const __half* __restrict__ Vp,
    __half* __restrict__ outp)
{
    extern __shared__ char sma[];
    const uint32_t sb = smem_u32(sma);
    const uint32_t sQ = sb;
    const int tid = threadIdx.x, wid = tid >> 5, lane = tid & 31;
    const int qt = (gridDim.x - 1) - blockIdx.x;    // heavy tiles first
    const int h = blockIdx.y, b = blockIdx.z;
    const int q0 = qt * 128;
    const size_t head = ((size_t)(b * Hn + h)) * Sn * 64;

    for (int i = tid; i < 1024; i += 256) {
        int row = i >> 3, c = i & 7;
        CP16(sQ + SWZ(row, c), Qp + head + (size_t)(q0 + row) * 64 + c * 8);
    }
    CP_COMMIT();

    auto issue_kv = [&](int kt) {
        uint32_t st = sb + 16384 + (uint32_t)(kt & (KVSTAGES - 1)) * 16384;
        const int k0 = kt * 64;
        for (int i = tid; i < 512; i += 256) {
            int row = i >> 3, c = i & 7;
            uint32_t d = SWZ(row, c);
            size_t g = head + (size_t)(k0 + row) * 64 + c * 8;
            CP16(st + d,        Kp + g);
            CP16(st + 8192 + d, Vp + g);
        }
        CP_COMMIT();
    };

    const int nkt = 2 * qt + 2;
#pragma unroll
    for (int kt = 0; kt < 3; kt++) {
        if (kt < nkt) issue_kv(kt); else CP_COMMIT();
    }
    CP_WAITG(3);
    __syncthreads();

    const int qr      = wid * 16 + (lane & 15);
    const int qc_add  = (lane >> 4);
    const int kr_base = ((lane >> 4) << 3) + (lane & 7);
    const int kc_add  = ((lane >> 3) & 1);
    const int vr      = (lane & 15);

    uint32_t qhr[4][4];
#pragma unroll
    for (int ks = 0; ks < 4; ks++)
        ldsm_x4(qhr[ks], sQ + SWZ(qr, 2 * ks + qc_add));

    float oacc[8][4];
#pragma unroll
    for (int j = 0; j < 8; j++)
#pragma unroll
        for (int q = 0; q < 4; q++) oacc[j][q] = 0.f;
    float m[2] = {-1e30f, -1e30f};
    float l[2] = {0.f, 0.f};

    for (int c = 0; c < nkt; c++) {
        CP_WAITG(2);
        __syncthreads();
        if (c + 3 < nkt) issue_kv(c + 3); else CP_COMMIT();

        const uint32_t stK = sb + 16384 + (uint32_t)(c & (KVSTAGES - 1)) * 16384;
        const uint32_t stV = stK + 8192;
        const int k0 = c * 64;

        float sacc[8][4];
#pragma unroll
        for (int j = 0; j < 8; j++)
#pragma unroll
            for (int q = 0; q < 4; q++) sacc[j][q] = 0.f;

#pragma unroll
        for (int ks = 0; ks < 4; ks++) {
#pragma unroll
            for (int kg = 0; kg < 4; kg++) {
                uint32_t kh4[4];
                ldsm_x4(kh4, stK + SWZ(kg * 16 + kr_base, 2 * ks + kc_add));
                mma_f16(sacc[2*kg],   qhr[ks], kh4[0], kh4[1]);
                mma_f16(sacc[2*kg+1], qhr[ks], kh4[2], kh4[3]);
            }
        }

        const int r0g = q0 + wid * 16 + (lane >> 2);
        if (k0 + 63 > q0 + wid * 16) {
#pragma unroll
            for (int j = 0; j < 8; j++) {
                int key = k0 + 8 * j + (lane & 3) * 2;
                if (key     > r0g)     sacc[j][0] = -1e30f;
                if (key + 1 > r0g)     sacc[j][1] = -1e30f;
                if (key     > r0g + 8) sacc[j][2] = -1e30f;
                if (key + 1 > r0g + 8) sacc[j][3] = -1e30f;
            }
        }

        uint32_t pp0[8], pp1[8];
#pragma unroll
        for (int rg = 0; rg < 2; rg++) {
            float tm = -1e30f;
#pragma unroll
            for (int j = 0; j < 8; j++)
                tm = fmaxf(tm, fmaxf(sacc[j][2*rg], sacc[j][2*rg+1]));
            tm = fmaxf(tm, __shfl_xor_sync(0xffffffffu, tm, 1));
            tm = fmaxf(tm, __shfl_xor_sync(0xffffffffu, tm, 2));
            float mnew = fmaxf(m[rg], tm);
            float corr = ex2(m[rg] - mnew);
            m[rg] = mnew;
            uint32_t rs2 = 0u;
#pragma unroll
            for (int j = 0; j < 8; j++) {
                uint32_t d = pack_f16(sacc[j][2*rg] - mnew, sacc[j][2*rg+1] - mnew);
                uint32_t e = ex2_h2(d);
                if (rg == 0) pp0[j] = e; else pp1[j] = e;
                rs2 = hadd2(rs2, e);
            }
            __half2 h2 = *(__half2*)&rs2;
            float rs = __low2float(h2) + __high2float(h2);
            l[rg] = l[rg] * corr + rs;
#pragma unroll
            for (int j = 0; j < 8; j++) {
                oacc[j][2*rg]   *= corr;
                oacc[j][2*rg+1] *= corr;
            }
        }

#pragma unroll
        for (int t = 0; t < 4; t++) {
            uint32_t phi[4];
            phi[0] = pp0[2*t];
            phi[1] = pp1[2*t];
            phi[2] = pp0[2*t+1];
            phi[3] = pp1[2*t+1];
            int vrow = t * 16 + vr;
#pragma unroll
            for (int p = 0; p < 4; p++) {
                uint32_t vh4[4];
                ldsm_x4_t(vh4, stV + SWZ(vrow, 2 * p + qc_add));
                mma_f16(oacc[2*p],   phi, vh4[0], vh4[1]);
                mma_f16(oacc[2*p+1], phi, vh4[2], vh4[3]);
            }
        }
    }

#pragma unroll
    for (int rg = 0; rg < 2; rg++) {
        l[rg] += __shfl_xor_sync(0xffffffffu, l[rg], 1);
        l[rg] += __shfl_xor_sync(0xffffffffu, l[rg], 2);
    }

    const float inv0 = 1.f / l[0], inv1 = 1.f / l[1];
    const int s0 = q0 + wid * 16 + (lane >> 2);
#pragma unroll
    for (int j = 0; j < 8; j++) {
        int dcol = h * 64 + 8 * j + (lane & 3) * 2;
        size_t i0 = (size_t)(b * Sn + s0) * HHD + dcol;
        size_t i1 = i0 + (size_t)8 * HHD;
        *(uint32_t*)&outp[i0] = pack_f16(oacc[j][0] * inv0, oacc[j][1] * inv0);
        *(uint32_t*)&outp[i1] = pack_f16(oacc[j][2] * inv1, oacc[j][3] * inv1);
    }
}

// ---------------------------------------------------------------------------
extern "C" void kernel_launch(void* const* d_in, const int* in_sizes, int n_in,
                              void* d_out, int out_size)
{
    const float* x      = (const float*)d_in[0];
    const float* w_qkv  = (const float*)d_in[1];
    const float* b_qkv  = (const float*)d_in[2];
    const float* w_proj = (const float*)d_in[3];
    const float* b_proj = (const float*)d_in[4];
    float* out = (float*)d_out;

    __half *xh, *wq, *wp, *att, *qq, *kk, *vv;
    cudaGetSymbolAddress((void**)&xh, g_x);
    cudaGetSymbolAddress((void**)&wq, g_wqkv);
    cudaGetSymbolAddress((void**)&wp, g_wproj);
    cudaGetSymbolAddress((void**)&att, g_att);
    cudaGetSymbolAddress((void**)&qq, g_q);
    cudaGetSymbolAddress((void**)&kk, g_k);
    cudaGetSymbolAddress((void**)&vv, g_v);

    cudaFuncSetAttribute(gemm_f16_kernel,
                         cudaFuncAttributeMaxDynamicSharedMemorySize, SMEM_G);
    cudaFuncSetAttribute(attn_mma_kernel,
                         cudaFuncAttributeMaxDynamicSharedMemorySize, ASMEM);

    // fused prep (x + both weights -> plain fp16)
    prep_kernel<<<(NX4 + NW14 + NW24) / 256, 256>>>(x, w_qkv, w_proj, xh, wq, wp);

    // 1) QKV GEMM -> head-major q(QSCALE)/k/v plain fp16
    gemm_f16_kernel<<<dim3(QKVROW / BN, Mrows / BM), GTH, SMEM_G>>>(
        xh, wq, b_qkv, nullptr, qq, kk, vv, Mrows, QKVROW, Dn, 1);

    // 2) tensor-core causal flash attention -> att plain fp16
    attn_mma_kernel<<<dim3(Sn / 128, Hn, Bn), 256, ASMEM>>>(qq, kk, vv, att);

    // 3) proj GEMM -> fp32 out + bias
    gemm_f16_kernel<<<dim3(Dn / BN, Mrows / BM), GTH, SMEM_G>>>(
        att, wp, b_proj, out, nullptr, nullptr, nullptr, Mrows, Dn, HHD, 0);
}